// round 2
// baseline (speedup 1.0000x reference)
#include <cuda_runtime.h>
#include <math.h>

// AttentionAggregator: sparse reformulation.
// features: [100000, 256] f32; nodes: [4096] i32; unique_ids: [16384] i32;
// neigh_idx: [4096, 10] i32. out: [4096, 256] f32.
//
// Per row: softmax over <=10 (deduplicated) neighbor dot products, then
// weighted sum of those embed rows. All masked columns are exactly 0 after
// softmax (exp(-9e15 - max) == 0 in fp32), so this matches the dense ref.

#define N_NODES 4096
#define FDIM    256
#define NSAMP   10

__global__ __launch_bounds__(320, 4)
void attn_agg_kernel(const float* __restrict__ feat,
                     const int*   __restrict__ nodes,
                     const int*   __restrict__ uids,
                     const int*   __restrict__ nidx,
                     float*       __restrict__ out)
{
    const int row  = blockIdx.x;
    const int tid  = threadIdx.x;
    const int warp = tid >> 5;
    const int lane = tid & 31;

    __shared__ float qf[FDIM];      // node feature row
    __shared__ int   cols[NSAMP];   // neigh columns
    __shared__ int   suid[NSAMP];   // vocab ids of neighbors
    __shared__ float dots[NSAMP];
    __shared__ float w[NSAMP];      // softmax weights (0 for dups)

    // Phase 0: load node feature row + neighbor columns
    const int node = nodes[row];
    if (tid < FDIM) qf[tid] = feat[(size_t)node * FDIM + tid];
    if (tid < NSAMP) cols[tid] = nidx[row * NSAMP + tid];
    __syncthreads();

    // Phase 1: warp s computes dot(q, embed[cols[s]]) over 256 dims.
    // float4 loads: lane reads v4[lane] and v4[lane+32] -> 2x LDG.128, coalesced.
    {
        const int c   = cols[warp];
        const int uid = uids[c];
        if (lane == 0) suid[warp] = uid;
        const float4* er4 = (const float4*)(feat + (size_t)uid * FDIM);
        const float4* qf4 = (const float4*)qf;
        float4 a0 = er4[lane];
        float4 a1 = er4[lane + 32];
        float4 q0 = qf4[lane];
        float4 q1 = qf4[lane + 32];
        float acc = a0.x * q0.x + a0.y * q0.y + a0.z * q0.z + a0.w * q0.w
                  + a1.x * q1.x + a1.y * q1.y + a1.z * q1.z + a1.w * q1.w;
        #pragma unroll
        for (int o = 16; o; o >>= 1)
            acc += __shfl_xor_sync(0xffffffffu, acc, o);
        if (lane == 0) dots[warp] = acc;
    }
    __syncthreads();

    // Phase 2: thread 0 dedups columns and computes softmax over distinct set.
    // Duplicate (row, col) pairs appear once in the dense mask -> count once.
    if (tid == 0) {
        bool dup[NSAMP];
        float m = -INFINITY;
        #pragma unroll
        for (int s = 0; s < NSAMP; s++) {
            bool d = false;
            for (int t = 0; t < s; t++) d |= (cols[t] == cols[s]);
            dup[s] = d;
            if (!d) m = fmaxf(m, dots[s]);
        }
        float sum = 0.f;
        #pragma unroll
        for (int s = 0; s < NSAMP; s++) {
            float e = dup[s] ? 0.f : __expf(dots[s] - m);
            w[s] = e;
            sum += e;
        }
        float inv = 1.f / sum;
        #pragma unroll
        for (int s = 0; s < NSAMP; s++) w[s] *= inv;
    }
    __syncthreads();

    // Phase 3: threads 0..255 accumulate out[row, f] = sum_s w[s]*embed[s][f].
    // Embed rows are L1/L2-hot from phase 1.
    if (tid < FDIM) {
        float acc = 0.f;
        #pragma unroll
        for (int s = 0; s < NSAMP; s++) {
            const float ws = w[s];
            if (ws != 0.f)
                acc += ws * feat[(size_t)suid[s] * FDIM + tid];
        }
        out[(size_t)row * FDIM + tid] = acc;
    }
}

extern "C" void kernel_launch(void* const* d_in, const int* in_sizes, int n_in,
                              void* d_out, int out_size)
{
    const float* feat  = (const float*)d_in[0];
    const int*   nodes = (const int*)  d_in[1];
    const int*   uids  = (const int*)  d_in[2];
    const int*   nidx  = (const int*)  d_in[3];
    float*       out   = (float*)d_out;
    (void)in_sizes; (void)n_in; (void)out_size;

    attn_agg_kernel<<<N_NODES, 320>>>(feat, nodes, uids, nidx, out);
}

// round 3
// speedup vs baseline: 1.8372x; 1.8372x over previous
#include <cuda_runtime.h>
#include <math.h>

// AttentionAggregator, warp-per-row register-resident version.
// features: [100000, 256] f32; nodes: [4096] i32; unique_ids: [16384] i32;
// neigh_idx: [4096, 10] i32. out: [4096, 256] f32.
//
// One warp per node row. Each lane holds 8 floats (2x float4) of the q row and
// of each of the 10 gathered embed rows -> all loads issued up front (MLP~22),
// no __syncthreads, softmax (with duplicate-column dedup, matching the dense
// mask's .set(1.0) semantics) computed redundantly on every lane, aggregation
// entirely from registers.

#define N_NODES 4096
#define FDIM    256
#define NSAMP   10
#define WARPS_PER_BLOCK 4

__global__ __launch_bounds__(WARPS_PER_BLOCK * 32)
void attn_agg_kernel(const float* __restrict__ feat,
                     const int*   __restrict__ nodes,
                     const int*   __restrict__ uids,
                     const int*   __restrict__ nidx,
                     float*       __restrict__ out)
{
    const int row  = blockIdx.x * WARPS_PER_BLOCK + (threadIdx.x >> 5);
    const int lane = threadIdx.x & 31;

    // --- index gathers (warp-uniform, independent, MLP=10) ---
    int cols[NSAMP];
    #pragma unroll
    for (int s = 0; s < NSAMP; s++)
        cols[s] = nidx[row * NSAMP + s];

    int uid[NSAMP];
    #pragma unroll
    for (int s = 0; s < NSAMP; s++)
        uid[s] = uids[cols[s]];

    // Dedup mask now, so cols regs die before the big row loads.
    // Duplicate (row, col) pairs appear once in the dense mask -> count once.
    unsigned dupmask = 0;
    #pragma unroll
    for (int s = 1; s < NSAMP; s++) {
        bool d = false;
        #pragma unroll
        for (int t = 0; t < NSAMP; t++)
            if (t < s) d |= (cols[t] == cols[s]);
        if (d) dupmask |= (1u << s);
    }

    const int node = nodes[row];

    // --- bulk loads: q row + 10 embed rows, all independent (22x LDG.128) ---
    const float4* qp = (const float4*)(feat + (size_t)node * FDIM);
    float4 q0 = qp[lane];
    float4 q1 = qp[lane + 32];

    float4 r0[NSAMP], r1[NSAMP];
    #pragma unroll
    for (int s = 0; s < NSAMP; s++) {
        const float4* ep = (const float4*)(feat + (size_t)uid[s] * FDIM);
        r0[s] = ep[lane];
        r1[s] = ep[lane + 32];
    }

    // --- 10 dot products, butterfly reduce (result on all lanes) ---
    float dots[NSAMP];
    #pragma unroll
    for (int s = 0; s < NSAMP; s++) {
        float a = r0[s].x * q0.x + r0[s].y * q0.y + r0[s].z * q0.z + r0[s].w * q0.w
                + r1[s].x * q1.x + r1[s].y * q1.y + r1[s].z * q1.z + r1[s].w * q1.w;
        #pragma unroll
        for (int o = 16; o; o >>= 1)
            a += __shfl_xor_sync(0xffffffffu, a, o);
        dots[s] = a;
    }

    // --- softmax over distinct columns (redundant on all lanes) ---
    float m = -INFINITY;
    #pragma unroll
    for (int s = 0; s < NSAMP; s++)
        if (!((dupmask >> s) & 1u)) m = fmaxf(m, dots[s]);

    float sum = 0.f;
    #pragma unroll
    for (int s = 0; s < NSAMP; s++) {
        float e = ((dupmask >> s) & 1u) ? 0.f : __expf(dots[s] - m);
        dots[s] = e;            // reuse as weight
        sum += e;
    }
    const float inv = 1.f / sum;

    // --- aggregation: pure register FMA, then 2x STG.128 ---
    float4 o0 = make_float4(0.f, 0.f, 0.f, 0.f);
    float4 o1 = make_float4(0.f, 0.f, 0.f, 0.f);
    #pragma unroll
    for (int s = 0; s < NSAMP; s++) {
        const float ws = dots[s] * inv;
        o0.x += ws * r0[s].x;  o0.y += ws * r0[s].y;
        o0.z += ws * r0[s].z;  o0.w += ws * r0[s].w;
        o1.x += ws * r1[s].x;  o1.y += ws * r1[s].y;
        o1.z += ws * r1[s].z;  o1.w += ws * r1[s].w;
    }

    float4* op = (float4*)(out + (size_t)row * FDIM);
    op[lane]      = o0;
    op[lane + 32] = o1;
}

extern "C" void kernel_launch(void* const* d_in, const int* in_sizes, int n_in,
                              void* d_out, int out_size)
{
    const float* feat  = (const float*)d_in[0];
    const int*   nodes = (const int*)  d_in[1];
    const int*   uids  = (const int*)  d_in[2];
    const int*   nidx  = (const int*)  d_in[3];
    float*       out   = (float*)d_out;
    (void)in_sizes; (void)n_in; (void)out_size;

    attn_agg_kernel<<<N_NODES / WARPS_PER_BLOCK, WARPS_PER_BLOCK * 32>>>(
        feat, nodes, uids, nidx, out);
}